// round 2
// baseline (speedup 1.0000x reference)
#include <cuda_runtime.h>

typedef unsigned long long ull;

// Problem constants
#define B_  32
#define C_  256
#define O_  256
#define KS  7
#define KK  49
#define H_  31
#define W_  31
#define HO  25
#define WO  25
#define HW  625
#define CKK (C_*KK)

// Tiling
#define BLOCK_O 64
#define BLOCK_P 128
#define TO 4
#define TP 8
#define THREADS 256
#define NPT 5
#define NOT 4
#define XROWS 12
#define XP 32                 // x pitch in float2 (channel pairs)
#define WROW (BLOCK_O*2 + 4)  // 132 floats per kl row (8B-pair aligned, 16B row-aligned)

__global__ __launch_bounds__(THREADS, 2)
void dwconv_f32x2_kernel(
    const float* __restrict__ x,      // [B,C,31,31]
    const float* __restrict__ kern,   // [B,C,7,7]
    const float* __restrict__ weight, // [O,C,7,7]
    const float* __restrict__ bias,   // [O]
    float* __restrict__ out)          // [B,O,25,25]
{
    const int blk = blockIdx.x;
    const int pt  = blk % NPT;
    const int ot  = (blk / NPT) % NOT;
    const int b   = blk / (NPT * NOT);

    const int p0 = pt * BLOCK_P;
    const int o0 = ot * BLOCK_O;

    const int tid = threadIdx.x;
    const int tx  = tid & 15;   // pixel group
    const int ty  = tid >> 4;   // o group

    __shared__ __align__(16) float2 xs[XROWS * XP];   // 3 KB   {x[c0], x[c1]}
    __shared__ __align__(16) float  wk[KK * WROW];    // 25.9 KB {w*k c0, w*k c1} pairs

    // ---- pixel geometry ----
    const int h_first = p0 / WO;
    const int p_last  = min(p0 + BLOCK_P - 1, HW - 1);
    const int h_last  = p_last / WO;
    const int nrows   = h_last - h_first + KS;   // <= 12

    int  pbase[TP];
    bool pvalid[TP];
    int  pidx[TP];
#pragma unroll
    for (int j = 0; j < TP; j++) {
        int p = p0 + tx + 16 * j;
        pvalid[j] = (p < HW);
        int pp = pvalid[j] ? p : p0;
        int ph = pp / WO;
        int pw = pp - ph * WO;
        pidx[j]  = pp;
        pbase[j] = (ph - h_first) * XP + pw;
    }

    ull acc[TO][TP];
#pragma unroll
    for (int oo = 0; oo < TO; oo++)
#pragma unroll
        for (int j = 0; j < TP; j++) acc[oo][j] = 0ULL;   // {0.f, 0.f}

    const float* xb = x      + (size_t)b * C_ * (H_ * W_);
    const float* kb = kern   + (size_t)b * C_ * KK;
    const float* wb = weight + (size_t)o0 * CKK;

    for (int cp = 0; cp < C_ / 2; cp++) {
        const int c0 = 2 * cp;
        // ---- stage x channel pair ----
        const float* xc0 = xb + (size_t)c0 * (H_ * W_);
        const float* xc1 = xc0 + (H_ * W_);
        const int nslots = nrows * XP;
        for (int i = tid; i < nslots; i += THREADS) {
            int r   = i >> 5;
            int col = i & 31;
            if (col < W_) {
                int g = (h_first + r) * W_ + col;
                xs[i] = make_float2(xc0[g], xc1[g]);
            }
        }
        // ---- stage modulated weight pairs ----
        const float* wc = wb + (size_t)c0 * KK;
        const float* kc = kb + (size_t)c0 * KK;
        for (int i = tid; i < KK * BLOCK_O; i += THREADS) {
            int o  = i / KK;
            int kl = i - o * KK;
            float w0 = wc[(size_t)o * CKK + kl]      * __ldg(kc + kl);
            float w1 = wc[(size_t)o * CKK + KK + kl] * __ldg(kc + KK + kl);
            *reinterpret_cast<float2*>(&wk[kl * WROW + 2 * o]) = make_float2(w0, w1);
        }
        __syncthreads();

        // ---- FFMA2 mainloop ----
#pragma unroll 1
        for (int ki = 0; ki < KS; ki++) {
#pragma unroll
            for (int kj = 0; kj < KS; kj++) {
                const int kl = ki * KS + kj;
                const ull* wp = reinterpret_cast<const ull*>(&wk[kl * WROW + ty * (2 * TO)]);
                ull w2[TO];
#pragma unroll
                for (int oo = 0; oo < TO; oo++) w2[oo] = wp[oo];
                const ull* xrow = reinterpret_cast<const ull*>(xs) + ki * XP + kj;
#pragma unroll
                for (int j = 0; j < TP; j++) {
                    ull xv = xrow[pbase[j]];
#pragma unroll
                    for (int oo = 0; oo < TO; oo++) {
                        asm("fma.rn.f32x2 %0, %1, %2, %0;"
                            : "+l"(acc[oo][j])
                            : "l"(w2[oo]), "l"(xv));
                    }
                }
            }
        }
        __syncthreads();
    }

    // ---- epilogue: reduce channel halves + bias ----
#pragma unroll
    for (int oo = 0; oo < TO; oo++) {
        const int o  = o0 + ty * TO + oo;
        const float bv = __ldg(bias + o);
        float* ob = out + ((size_t)b * O_ + o) * HW;
#pragma unroll
        for (int j = 0; j < TP; j++) {
            if (pvalid[j]) {
                float lo, hi;
                asm("mov.b64 {%0, %1}, %2;" : "=f"(lo), "=f"(hi) : "l"(acc[oo][j]));
                ob[pidx[j]] = lo + hi + bv;
            }
        }
    }
}

extern "C" void kernel_launch(void* const* d_in, const int* in_sizes, int n_in,
                              void* d_out, int out_size) {
    const float* x      = (const float*)d_in[0];
    const float* kernel = (const float*)d_in[1];
    const float* weight = (const float*)d_in[2];
    const float* bias   = (const float*)d_in[3];
    float* out = (float*)d_out;

    const int grid = B_ * NOT * NPT;   // 640 blocks
    dwconv_f32x2_kernel<<<grid, THREADS>>>(x, kernel, weight, bias, out);
}

// round 4
// speedup vs baseline: 1.8375x; 1.8375x over previous
#include <cuda_runtime.h>
#include <cuda_bf16.h>
#include <cstdint>

#define B_  32
#define C_  256
#define O_  256
#define KK  49
#define HW  625
#define WO  25
#define CKK 12544

#define MT 128
#define NT 128
#define THREADS 256
#define PITCH  72                    // bf16 elems per smem row (64 + 8 pad)
#define PITCHB 144                   // bytes per row
#define HALF_BYTES (128 * PITCHB)    // 18432: one hi or lo tile
#define TILE_BYTES (2 * HALF_BYTES)  // 36864: hi + lo

#define SM_X    0                    // 12*32 floats = 1536 B
#define SM_K    1536                 // 49 floats
#define SM_OFFS 1792                 // 64 ints
#define SM_A    2048                 // 2 * 36864
#define SM_B    (SM_A + 2 * TILE_BYTES)    // 75776
#define SMEM_DYN (SM_B + 2 * TILE_BYTES)   // 149504

// Precomputed bf16 hi/lo weight tiles, padded rows: [o_tile][c][half][o][kl]
__device__ __nv_bfloat16 g_W[2][C_][2][128][PITCH];

__device__ __forceinline__ uint32_t smem_u32(const void* p) {
    uint32_t a;
    asm("{ .reg .u64 t; cvta.to.shared.u64 t, %1; cvt.u32.u64 %0, t; }" : "=r"(a) : "l"(p));
    return a;
}
__device__ __forceinline__ void ldsm4(uint32_t* r, uint32_t addr) {
    asm volatile("ldmatrix.sync.aligned.m8n8.x4.shared.b16 {%0,%1,%2,%3}, [%4];"
                 : "=r"(r[0]), "=r"(r[1]), "=r"(r[2]), "=r"(r[3]) : "r"(addr));
}
__device__ __forceinline__ void mma_bf16(float* d, const uint32_t* a, const uint32_t* b) {
    asm volatile("mma.sync.aligned.m16n8k16.row.col.f32.bf16.bf16.f32 "
                 "{%0,%1,%2,%3}, {%4,%5,%6,%7}, {%8,%9}, {%0,%1,%2,%3};"
                 : "+f"(d[0]), "+f"(d[1]), "+f"(d[2]), "+f"(d[3])
                 : "r"(a[0]), "r"(a[1]), "r"(a[2]), "r"(a[3]), "r"(b[0]), "r"(b[1]));
}
#define CP16(dst, src) \
    asm volatile("cp.async.cg.shared.global [%0], [%1], 16;" :: "r"(dst), "l"(src) : "memory")

// ---- precompute: split weights into bf16 hi/lo padded tiles ----
__global__ void precompute_w(const float* __restrict__ w) {
    int idx = blockIdx.x * 256 + threadIdx.x;   // [t][c][o][kl]
    int kl = idx % PITCH;
    int r  = idx / PITCH;
    int o  = r & 127;
    int c  = (r >> 7) & 255;
    int t  = r >> 15;
    if (t >= 2) return;
    float v = (kl < KK) ? w[(size_t)(t * 128 + o) * CKK + c * KK + kl] : 0.f;
    __nv_bfloat16 h = __float2bfloat16_rn(v);
    float lres = v - __bfloat162float(h);
    g_W[t][c][0][o][kl] = h;
    g_W[t][c][1][o][kl] = __float2bfloat16_rn(lres);
}

// ---- main kernel ----
__global__ __launch_bounds__(THREADS)
void dwconv_hmma(const float* __restrict__ x, const float* __restrict__ kern,
                 const float* __restrict__ bias, float* __restrict__ out)
{
    extern __shared__ __align__(128) char smem[];
    const uint32_t sbase = smem_u32(smem);

    const int tid = threadIdx.x, wid = tid >> 5, lid = tid & 31;
    const int blk = blockIdx.x;
    const int pt = blk % 5, t = (blk / 5) & 1, b = blk / 10;
    const int p0 = pt * NT, o0 = t * MT;
    const int h0 = p0 / WO;

    float* xsm = (float*)(smem + SM_X);
    float* ksm = (float*)(smem + SM_K);
    int*   offs = (int*)(smem + SM_OFFS);

    if (tid < 64) offs[tid] = (tid < KK) ? (tid / 7) * 32 + (tid % 7) : -1;

    // warp position: 2 (M) x 4 (N)
    const int mw = wid >> 2, nw = wid & 3;
    const uint32_t aoff = (uint32_t)((mw * 64 + (lid & 15)) * PITCHB) + ((lid & 16) ? 16u : 0u);
    const uint32_t boff = (uint32_t)((nw * 32 + (lid & 7) + ((lid & 16) ? 8 : 0)) * PITCHB)
                        + ((lid & 8) ? 16u : 0u);

    float acc[4][4][4];
#pragma unroll
    for (int mi = 0; mi < 4; mi++)
#pragma unroll
        for (int nj = 0; nj < 4; nj++)
#pragma unroll
            for (int q = 0; q < 4; q++) acc[mi][nj][q] = 0.f;

    const float* xb = x    + (size_t)b * C_ * 961;
    const float* kb = kern + (size_t)b * C_ * KK;

    // prefetch channel 0 x/kern into regs (12 rows * 31 = 372 floats)
    float xr0 = 0.f, xr1 = 0.f, kr = 0.f;
    {
        const float* xc = xb;
        int i1 = tid + 256;
        if (tid < 372 && h0 * 31 + tid < 961) xr0 = xc[h0 * 31 + tid];
        if (i1 < 372 && h0 * 31 + i1 < 961)   xr1 = xc[h0 * 31 + i1];
        if (tid < KK) kr = kb[tid];
    }
    // cp.async A(0)
    {
        const char* asrc = (const char*)&g_W[t][0][0][0][0];
        uint32_t adst = sbase + SM_A;
#pragma unroll
        for (int i = 0; i < 9; i++) {
            int off = (i * 256 + tid) * 16;
            CP16(adst + off, asrc + off);
        }
        asm volatile("cp.async.commit_group;" ::: "memory");
    }

#pragma unroll 1
    for (int c = 0; c < C_; c++) {
        const int buf = c & 1;

        // ---- stage x / kern from regs ----
        {
            int i1 = tid + 256;
            if (tid < 372) { int r = tid / 31; xsm[r * 32 + (tid - r * 31)] = xr0; }
            if (i1 < 372)  { int r = i1 / 31;  xsm[r * 32 + (i1 - r * 31)]  = xr1; }
            if (tid < KK) ksm[tid] = kr;
        }
        __syncthreads();   // xsm/ksm visible; prev mma done

        // ---- build modulated B tile (bf16 hi/lo) ----
        {
            char* bhi = smem + SM_B + buf * TILE_BYTES;
            char* blo = bhi + HALF_BYTES;
#pragma unroll
            for (int tb = 0; tb < 4; tb++) {
                int task = tb * 256 + tid;          // 1024 tasks: 128 p x 8 chunks
                int p  = task >> 3;
                int ch = task & 7;
                int pg = p0 + p;
                uint4 hv = make_uint4(0, 0, 0, 0);
                uint4 lv = make_uint4(0, 0, 0, 0);
                if (pg < HW) {
                    int phh = pg / WO, pw = pg - phh * WO;
                    int rbase = (phh - h0) * 32 + pw;
                    uint32_t hp[4], lp[4];
#pragma unroll
                    for (int j2 = 0; j2 < 4; j2++) {
                        int kla = ch * 8 + 2 * j2;
                        int klb = kla + 1;
                        int oa = offs[kla], ob = offs[klb];
                        float v0 = (oa >= 0) ? xsm[rbase + oa] * ksm[kla] : 0.f;
                        float v1 = (ob >= 0) ? xsm[rbase + ob] * ksm[klb] : 0.f;
                        __nv_bfloat162 hh = __floats2bfloat162_rn(v0, v1);
                        float l0 = v0 - __bfloat162float(hh.x);
                        float l1 = v1 - __bfloat162float(hh.y);
                        __nv_bfloat162 ll = __floats2bfloat162_rn(l0, l1);
                        hp[j2] = *(uint32_t*)&hh;
                        lp[j2] = *(uint32_t*)&ll;
                    }
                    hv = make_uint4(hp[0], hp[1], hp[2], hp[3]);
                    lv = make_uint4(lp[0], lp[1], lp[2], lp[3]);
                }
                uint32_t woff = (uint32_t)(p * PITCHB + ch * 16);
                *(uint4*)(bhi + woff) = hv;
                *(uint4*)(blo + woff) = lv;
            }
        }

        // ---- prefetch next channel x/kern ----
        if (c + 1 < C_) {
            const float* xc = xb + (size_t)(c + 1) * 961;
            int i1 = tid + 256;
            xr0 = (tid < 372 && h0 * 31 + tid < 961) ? xc[h0 * 31 + tid] : 0.f;
            xr1 = (i1 < 372 && h0 * 31 + i1 < 961)   ? xc[h0 * 31 + i1]  : 0.f;
            kr  = (tid < KK) ? kb[(size_t)(c + 1) * KK + tid] : 0.f;
        }

        asm volatile("cp.async.wait_group 0;" ::: "memory");
        __syncthreads();   // A(c) + B(c) ready

        // ---- cp.async A(c+1) ----
        if (c + 1 < C_) {
            const char* asrc = (const char*)&g_W[t][c + 1][0][0][0];
            uint32_t adst = sbase + SM_A + ((c + 1) & 1) * TILE_BYTES;
#pragma unroll
            for (int i = 0; i < 9; i++) {
                int off = (i * 256 + tid) * 16;
                CP16(adst + off, asrc + off);
            }
            asm volatile("cp.async.commit_group;" ::: "memory");
        }

        // ---- MMA: 4 k-steps x (4 mi x 4 nj) x 3 products ----
        const uint32_t abuf = sbase + SM_A + buf * TILE_BYTES + aoff;
        const uint32_t bbuf = sbase + SM_B + buf * TILE_BYTES + boff;
#pragma unroll
        for (int k = 0; k < 4; k++) {
            const uint32_t ak = abuf + k * 32;
            const uint32_t bk = bbuf + k * 32;
            uint32_t Ah[4][4], Al[4][4], Bh[8], Bl[8];
#pragma unroll
            for (int mi = 0; mi < 4; mi++) {
                ldsm4(Ah[mi], ak + mi * 2304);
                ldsm4(Al[mi], ak + mi * 2304 + HALF_BYTES);
            }
            ldsm4(&Bh[0], bk);
            ldsm4(&Bh[4], bk + 2304);
            ldsm4(&Bl[0], bk + HALF_BYTES);
            ldsm4(&Bl[4], bk + 2304 + HALF_BYTES);
#pragma unroll
            for (int mi = 0; mi < 4; mi++)
#pragma unroll
                for (int nj = 0; nj < 4; nj++) {
                    mma_bf16(acc[mi][nj], Ah[mi], &Bh[nj * 2]);
                    mma_bf16(acc[mi][nj], Ah[mi], &Bl[nj * 2]);
                    mma_bf16(acc[mi][nj], Al[mi], &Bh[nj * 2]);
                }
        }
    }

    // ---- epilogue ----
#pragma unroll
    for (int mi = 0; mi < 4; mi++) {
        int o_lo = o0 + mw * 64 + mi * 16 + (lid >> 2);
        float bv0 = __ldg(bias + o_lo);
        float bv1 = __ldg(bias + o_lo + 8);
        float* r0 = out + ((size_t)b * O_ + o_lo) * HW;
        float* r1 = r0 + 8 * HW;
#pragma unroll
        for (int nj = 0; nj < 4; nj++) {
            int p = p0 + nw * 32 + nj * 8 + 2 * (lid & 3);
            if (p < HW)     r0[p]     = acc[mi][nj][0] + bv0;
            if (p + 1 < HW) r0[p + 1] = acc[mi][nj][1] + bv0;
            if (p < HW)     r1[p]     = acc[mi][nj][2] + bv1;
            if (p + 1 < HW) r1[p + 1] = acc[mi][nj][3] + bv1;
        }
    }
}

extern "C" void kernel_launch(void* const* d_in, const int* in_sizes, int n_in,
                              void* d_out, int out_size) {
    const float* x      = (const float*)d_in[0];
    const float* kernel = (const float*)d_in[1];
    const float* weight = (const float*)d_in[2];
    const float* bias   = (const float*)d_in[3];
    float* out = (float*)d_out;

    cudaFuncSetAttribute(dwconv_hmma, cudaFuncAttributeMaxDynamicSharedMemorySize, SMEM_DYN);

    precompute_w<<<18432, 256>>>(weight);
    dwconv_hmma<<<B_ * 2 * 5, THREADS, SMEM_DYN>>>(x, kernel, bias, out);
}

// round 5
// speedup vs baseline: 3.2668x; 1.7778x over previous
#include <cuda_runtime.h>
#include <cuda_fp16.h>
#include <cstdint>

#define B_  32
#define C_  256
#define O_  256
#define KK  49
#define HW  625
#define WO  25
#define CKK 12544

#define THREADS 512
#define NGROUP  128          // channel pairs
#define KG      112          // padded K per group (98 real)
#define KSTEPS  7
#define PITCH   120          // fp16 per row (112 + 8 pad)
#define PITCHB  240
#define A_HALF  30720        // 128 rows * 240B
#define A_BUF   61440        // hi + lo
#define B_BUF   30720        // hi only

#define SM_A    0
#define SM_B    122880
#define SM_X    184320       // 2 buf * 768 floats
#define SM_KM   190464       // 2 buf * 112 floats
#define SM_XOFF 191360       // 112 ints
#define SM_RTAB 191808       // 128 ints
#define SMEM_DYN 192320

// Precomputed fp16 hi/lo weights (scaled x256): [t][g][half][o 128][k 120]
__device__ __half g_W[2][NGROUP][2][128][PITCH];

__device__ __forceinline__ uint32_t smem_u32(const void* p) {
    uint32_t a;
    asm("{ .reg .u64 t; cvta.to.shared.u64 t, %1; cvt.u32.u64 %0, t; }" : "=r"(a) : "l"(p));
    return a;
}
__device__ __forceinline__ void ldsm4(uint32_t* r, uint32_t addr) {
    asm volatile("ldmatrix.sync.aligned.m8n8.x4.shared.b16 {%0,%1,%2,%3}, [%4];"
                 : "=r"(r[0]), "=r"(r[1]), "=r"(r[2]), "=r"(r[3]) : "r"(addr));
}
__device__ __forceinline__ void mma_f16(float* d, const uint32_t* a, const uint32_t* b) {
    asm volatile("mma.sync.aligned.m16n8k16.row.col.f32.f16.f16.f32 "
                 "{%0,%1,%2,%3}, {%4,%5,%6,%7}, {%8,%9}, {%0,%1,%2,%3};"
                 : "+f"(d[0]), "+f"(d[1]), "+f"(d[2]), "+f"(d[3])
                 : "r"(a[0]), "r"(a[1]), "r"(a[2]), "r"(a[3]), "r"(b[0]), "r"(b[1]));
}
#define CP16(dst, src) \
    asm volatile("cp.async.cg.shared.global [%0], [%1], 16;" :: "r"(dst), "l"(src) : "memory")

// ---- precompute: fp16 hi/lo split of (256*weight), packed 2 channels/group ----
__global__ void precompute_w(const float* __restrict__ w) {
    long idx = (long)blockIdx.x * 256 + threadIdx.x;
    int k = idx % KG;
    int o = (idx / KG) & 127;
    int g = (idx / (KG * 128)) & 127;
    int t = (int)(idx / ((long)KG * 128 * NGROUP));
    if (t >= 2) return;
    float v = 0.f;
    if (k < 98) {
        int ci = k / 49, kl = k - ci * 49;
        v = w[(size_t)(t * 128 + o) * CKK + (g * 2 + ci) * KK + kl] * 256.f;
    }
    __half h = __float2half_rn(v);
    __half l = __float2half_rn(v - __half2float(h));
    g_W[t][g][0][o][k] = h;
    g_W[t][g][1][o][k] = l;
}

// ---- main kernel ----
__global__ __launch_bounds__(THREADS, 1)
void dwconv_hmma2(const float* __restrict__ x, const float* __restrict__ kern,
                  const float* __restrict__ bias, float* __restrict__ out)
{
    extern __shared__ __align__(128) char smem[];
    const uint32_t sbase = smem_u32(smem);

    const int tid = threadIdx.x, wid = tid >> 5, lid = tid & 31;
    const int mw = wid >> 2, nw = wid & 3;
    const int blk = blockIdx.x;
    const int pt = blk % 5, t = (blk / 5) & 1, b = blk / 10;
    const int p0 = pt * 128, o0 = t * 128;
    const int h0 = p0 / WO;

    int*   xoffs = (int*)(smem + SM_XOFF);
    int*   rtab  = (int*)(smem + SM_RTAB);

    // static tables
    if (tid < KG) {
        int v = 0;
        if (tid < 98) {
            int ci = tid >= 49;
            int kl = tid - ci * 49;
            v = ci * 384 + (kl / 7) * 32 + (kl % 7);
        }
        xoffs[tid] = v;
    }
    if (tid < 128) {
        int pg = p0 + tid;
        rtab[tid] = (pg < HW) ? ((pg / WO) - h0) * 32 + (pg % WO) : -1;
    }

    const float* xb = x    + (size_t)b * C_ * 961;
    const float* kb = kern + (size_t)b * CKK;

    // prefetch group 0 x (2 channels, 372 floats each) + kern (98) into regs
    float xr0 = 0.f, xr1 = 0.f, kr = 0.f;
    {
        if (tid < 744) {
            int ch = tid >= 372, ii = tid - ch * 372;
            if (h0 * 31 + ii < 961) xr0 = xb[(size_t)ch * 961 + h0 * 31 + ii];
        }
        if (tid < 232) {
            int ii = tid + 512 - 372;
            if (h0 * 31 + ii < 961) xr1 = xb[961 + h0 * 31 + ii];
        }
        if (tid < 98) kr = kb[tid];
    }
    // cp.async A(0)
    {
        const char* src = (const char*)&g_W[t][0][0][0][0];
#pragma unroll
        for (int i = 0; i < 8; i++) {
            int idx = i * 512 + tid;
            if (idx < 3840) CP16(sbase + SM_A + idx * 16, src + idx * 16);
        }
        asm volatile("cp.async.commit_group;" ::: "memory");
    }

    float acc[2][4][4];
#pragma unroll
    for (int mi = 0; mi < 2; mi++)
#pragma unroll
        for (int nj = 0; nj < 4; nj++)
#pragma unroll
            for (int q = 0; q < 4; q++) acc[mi][nj][q] = 0.f;

    const uint32_t apat = (uint32_t)(mw * 32 * PITCHB + (lid & 15) * PITCHB + (lid >> 4) * 16);
    const uint32_t bpat = (uint32_t)((nw * 32 + (lid & 7) + ((lid & 16) ? 8 : 0)) * PITCHB
                                     + ((lid & 8) ? 16 : 0));

#pragma unroll 1
    for (int g = 0; g < NGROUP; g++) {
        const int buf = g & 1;

        // ---- stage x + kmod into smem ----
        float* xs = (float*)(smem + SM_X + buf * 3072);
        float* km = (float*)(smem + SM_KM + buf * 448);
        if (tid < 744) {
            int ch = tid >= 372, ii = tid - ch * 372;
            xs[ch * 384 + (ii / 31) * 32 + (ii % 31)] = xr0;
        }
        if (tid < 232) {
            int ii = tid + 512 - 372;
            xs[384 + (ii / 31) * 32 + (ii % 31)] = xr1;
        }
        if (tid < KG) km[tid] = (tid < 98) ? kr : 0.f;
        __syncthreads();

        // ---- build B hi tile: 128 p x 112 k fp16 ----
        {
            char* bt = smem + SM_B + buf * B_BUF;
#pragma unroll
            for (int it = 0; it < 4; it++) {
                int task = it * 512 + tid;
                if (task < 1792) {
                    int ch = task >> 7, p = task & 127;
                    int rb = rtab[p];
                    uint4 val = make_uint4(0, 0, 0, 0);
                    if (rb >= 0) {
                        int k0 = ch * 8;
                        const float4 km0 = *(const float4*)(km + k0);
                        const float4 km1 = *(const float4*)(km + k0 + 4);
                        const int4 xo0 = *(const int4*)(xoffs + k0);
                        const int4 xo1 = *(const int4*)(xoffs + k0 + 4);
                        float v0 = xs[rb + xo0.x] * km0.x;
                        float v1 = xs[rb + xo0.y] * km0.y;
                        float v2 = xs[rb + xo0.z] * km0.z;
                        float v3 = xs[rb + xo0.w] * km0.w;
                        float v4 = xs[rb + xo1.x] * km1.x;
                        float v5 = xs[rb + xo1.y] * km1.y;
                        float v6 = xs[rb + xo1.z] * km1.z;
                        float v7 = xs[rb + xo1.w] * km1.w;
                        __half2 h0 = __floats2half2_rn(v0, v1);
                        __half2 h1 = __floats2half2_rn(v2, v3);
                        __half2 h2 = __floats2half2_rn(v4, v5);
                        __half2 h3 = __floats2half2_rn(v6, v7);
                        val = make_uint4(*(uint32_t*)&h0, *(uint32_t*)&h1,
                                         *(uint32_t*)&h2, *(uint32_t*)&h3);
                    }
                    *(uint4*)(bt + p * PITCHB + ch * 16) = val;
                }
            }
        }

        // ---- prefetch next group x/kern into regs ----
        if (g + 1 < NGROUP) {
            const float* xc = xb + (size_t)(g + 1) * 2 * 961;
            xr0 = xr1 = kr = 0.f;
            if (tid < 744) {
                int ch = tid >= 372, ii = tid - ch * 372;
                if (h0 * 31 + ii < 961) xr0 = xc[(size_t)ch * 961 + h0 * 31 + ii];
            }
            if (tid < 232) {
                int ii = tid + 512 - 372;
                if (h0 * 31 + ii < 961) xr1 = xc[961 + h0 * 31 + ii];
            }
            if (tid < 98) kr = kb[(size_t)(g + 1) * 98 + tid];
        }

        asm volatile("cp.async.wait_group 0;" ::: "memory");
        __syncthreads();    // A(g) + B(g) ready

        // ---- issue cp.async A(g+1) ----
        if (g + 1 < NGROUP) {
            const char* src = (const char*)&g_W[t][g + 1][0][0][0];
            uint32_t dst = sbase + SM_A + ((g + 1) & 1) * A_BUF;
#pragma unroll
            for (int i = 0; i < 8; i++) {
                int idx = i * 512 + tid;
                if (idx < 3840) CP16(dst + idx * 16, src + idx * 16);
            }
            asm volatile("cp.async.commit_group;" ::: "memory");
        }

        // ---- MMA: 7 k-steps, 2 products (Ah + Al) x Bh ----
        const uint32_t ab = sbase + SM_A + buf * A_BUF + apat;
        const uint32_t bb = sbase + SM_B + buf * B_BUF + bpat;
#pragma unroll
        for (int k = 0; k < KSTEPS; k++) {
            uint32_t Ah0[4], Ah1[4], Al0[4], Al1[4], Bv[8];
            ldsm4(Ah0, ab + k * 32);
            ldsm4(Ah1, ab + 16 * PITCHB + k * 32);
            ldsm4(Al0, ab + A_HALF + k * 32);
            ldsm4(Al1, ab + A_HALF + 16 * PITCHB + k * 32);
            ldsm4(&Bv[0], bb + k * 32);
            ldsm4(&Bv[4], bb + 16 * PITCHB + k * 32);
#pragma unroll
            for (int nj = 0; nj < 4; nj++) {
                mma_f16(acc[0][nj], Ah0, &Bv[nj * 2]);
                mma_f16(acc[1][nj], Ah1, &Bv[nj * 2]);
                mma_f16(acc[0][nj], Al0, &Bv[nj * 2]);
                mma_f16(acc[1][nj], Al1, &Bv[nj * 2]);
            }
        }
    }

    // ---- epilogue: unscale, bias, store ----
    const float s = 1.0f / 256.0f;
#pragma unroll
    for (int mi = 0; mi < 2; mi++) {
        int o = o0 + mw * 32 + mi * 16 + (lid >> 2);
        float bv0 = __ldg(bias + o);
        float bv1 = __ldg(bias + o + 8);
        float* r0 = out + ((size_t)b * O_ + o) * HW;
        float* r1 = r0 + 8 * HW;
#pragma unroll
        for (int nj = 0; nj < 4; nj++) {
            int p = p0 + nw * 32 + nj * 8 + 2 * (lid & 3);
            if (p < HW)     r0[p]     = acc[mi][nj][0] * s + bv0;
            if (p + 1 < HW) r0[p + 1] = acc[mi][nj][1] * s + bv0;
            if (p < HW)     r1[p]     = acc[mi][nj][2] * s + bv1;
            if (p + 1 < HW) r1[p + 1] = acc[mi][nj][3] * s + bv1;
        }
    }
}

extern "C" void kernel_launch(void* const* d_in, const int* in_sizes, int n_in,
                              void* d_out, int out_size) {
    const float* x      = (const float*)d_in[0];
    const float* kernel = (const float*)d_in[1];
    const float* weight = (const float*)d_in[2];
    const float* bias   = (const float*)d_in[3];
    float* out = (float*)d_out;

    cudaFuncSetAttribute(dwconv_hmma2, cudaFuncAttributeMaxDynamicSharedMemorySize, SMEM_DYN);

    // 2 * 128 * 128 * 112 = 3,670,016 elements
    precompute_w<<<14336, 256>>>(weight);
    dwconv_hmma2<<<B_ * 2 * 5, THREADS, SMEM_DYN>>>(x, kernel, bias, out);
}